// round 1
// baseline (speedup 1.0000x reference)
#include <cuda_runtime.h>
#include <math.h>

#define BATCH 2
#define SEQ   2048
#define NH    12
#define HD    64
#define EMB   768     // NH*HD
#define PLMD  1280
#define SD    128
#define FFD   640
#define ROWS  (BATCH*SEQ)                 // 4096
#define OUT_ELEMS ((long)ROWS*PLMD)       // 5,242,880
#define LOG2_10000 13.287712379549449f

// ---------------- scratch (static __device__, no allocation) ----------------
__device__ float g_qp[ROWS*EMB];
__device__ float g_kp[ROWS*EMB];
__device__ float g_vp[ROWS*EMB];
__device__ float g_qh[ROWS*EMB];   // [B,H,S,D] roped
__device__ float g_kh[ROWS*EMB];   // [B,H,S,D] roped
__device__ float g_vt[ROWS*EMB];   // [B,H,D,S]
__device__ float g_av[ROWS*EMB];   // [B,H,S,D]
__device__ float g_vals[ROWS*EMB]; // [B,S,E]
__device__ float g_x[ROWS*PLMD];
__device__ float g_ln[ROWS*PLMD];
__device__ float g_ff[ROWS*FFD];

// ---------------- generic fp32 tiled GEMM: C = alpha*A@B^T (+bias)(+extra)(gelu) ----
// A element (m,k) at A[m*sAm + k*sAk]; B element (n,k) at B[n*sBn + k*sBk].
// EPI: 0 = +bias, 1 = +bias+extra, 2 = gelu(+bias)
template<int EPI, int BM, int BN, int TM, int TN>
__global__ __launch_bounds__(256)
void gemm_kernel(const float* __restrict__ A, const float* __restrict__ B,
                 const float* __restrict__ bias, const float* __restrict__ extra,
                 float* __restrict__ C,
                 int M, int N, int K,
                 int sAm, int sAk, int sBn, int sBk, int ldc,
                 long zA, long zB, long zC, float alpha)
{
    constexpr int BK  = 16;
    constexpr int NTX = BN / TN;
    constexpr int NT  = (BM/TM)*(BN/TN);   // must be 256
    __shared__ __align__(16) float As[BK][BM+4];
    __shared__ __align__(16) float Bs[BK][BN+4];

    int tid = threadIdx.x;
    int tx = tid % NTX, ty = tid / NTX;
    int row0 = blockIdx.y * BM, col0 = blockIdx.x * BN;
    A += (long)blockIdx.z * zA;
    B += (long)blockIdx.z * zB;
    C += (long)blockIdx.z * zC;

    float acc[TM][TN];
#pragma unroll
    for (int i = 0; i < TM; i++)
#pragma unroll
        for (int j = 0; j < TN; j++) acc[i][j] = 0.f;

    for (int k0 = 0; k0 < K; k0 += BK) {
#pragma unroll
        for (int i = 0; i < BM*BK/NT; i++) {
            int idx = tid + i*NT;
            int k = idx & (BK-1), m = idx >> 4;
            As[k][m] = A[(long)(row0+m)*sAm + (long)(k0+k)*sAk];
        }
#pragma unroll
        for (int i = 0; i < BN*BK/NT; i++) {
            int idx = tid + i*NT;
            int k = idx & (BK-1), n = idx >> 4;
            Bs[k][n] = B[(long)(col0+n)*sBn + (long)(k0+k)*sBk];
        }
        __syncthreads();
#pragma unroll
        for (int kk = 0; kk < BK; kk++) {
            float a[TM], bb[TN];
#pragma unroll
            for (int i = 0; i < TM; i++) a[i] = As[kk][ty*TM+i];
#pragma unroll
            for (int j = 0; j < TN; j++) bb[j] = Bs[kk][tx*TN+j];
#pragma unroll
            for (int i = 0; i < TM; i++)
#pragma unroll
                for (int j = 0; j < TN; j++)
                    acc[i][j] = fmaf(a[i], bb[j], acc[i][j]);
        }
        __syncthreads();
    }

#pragma unroll
    for (int i = 0; i < TM; i++) {
        int m = row0 + ty*TM + i;
#pragma unroll
        for (int j = 0; j < TN; j++) {
            int n = col0 + tx*TN + j;
            float v = alpha * acc[i][j];
            if (bias) v += bias[n];
            if (EPI == 1) v += extra[(long)m*ldc + n];
            if (EPI == 2) v = 0.5f * v * (1.f + erff(v * 0.70710678118654752f));
            C[(long)m*ldc + n] = v;
        }
    }
}

// ---------------- head split (+ optional RoPE / V transpose) ----------------
// MODE 0: [B,S,H*D] -> [B,H,S,D]
// MODE 1: same, with RoPE applied
// MODE 2: [B,S,H*D] -> [B,H,D,S]   (for V, so AV B-loads coalesce)
template<int MODE>
__global__ void head_split_kernel(const float* __restrict__ src, float* __restrict__ dst)
{
    int idx = blockIdx.x * blockDim.x + threadIdx.x;
    if (idx >= ROWS*EMB) return;
    int d = idx & 63;
    int s = (idx >> 6) & (SEQ-1);
    int t = idx >> 17;           // 6+11 bits
    int h = t % NH;
    int b = t / NH;
    long srcoff = (long)(b*SEQ + s)*EMB + h*HD + d;
    float val;
    if (MODE == 1) {
        int j = d & 31;
        float inv = exp2f(-(float)j * (LOG2_10000 / 32.0f));  // 10000^{-2j/64}
        float freq = (float)s * inv;
        float sn, c;
        sincosf(freq, &sn, &c);
        float x = src[srcoff];
        float pr = (d < 32) ? -src[srcoff + 32] : src[srcoff - 32];
        val = x*c + pr*sn;
    } else {
        val = src[srcoff];
    }
    if (MODE == 2)
        dst[((long)(b*NH + h)*HD + d)*SEQ + s] = val;
    else
        dst[idx] = val;
}

// ---------------- merge heads: [B,H,S,D] -> [B,S,H*D] ----------------
__global__ void merge_heads_kernel(const float* __restrict__ src, float* __restrict__ dst)
{
    int idx = blockIdx.x * blockDim.x + threadIdx.x;
    if (idx >= ROWS*EMB) return;
    int d = idx & 63;
    int s = (idx >> 6) & (SEQ-1);
    int t = idx >> 17;
    int h = t % NH;
    int b = t / NH;
    dst[(long)(b*SEQ + s)*EMB + h*HD + d] = src[idx];
}

// ---------------- row softmax over 2048 cols, in place ----------------
__global__ __launch_bounds__(256) void softmax_kernel(float* __restrict__ att)
{
    __shared__ float red[256];
    long row = blockIdx.x;
    float* x = att + row * SEQ;
    int tid = threadIdx.x;
    float v[8];
    float m = -1e30f;
#pragma unroll
    for (int j = 0; j < 8; j++) { v[j] = x[tid + j*256]; m = fmaxf(m, v[j]); }
    red[tid] = m; __syncthreads();
    for (int s = 128; s > 0; s >>= 1) { if (tid < s) red[tid] = fmaxf(red[tid], red[tid+s]); __syncthreads(); }
    m = red[0]; __syncthreads();
    float sum = 0.f;
#pragma unroll
    for (int j = 0; j < 8; j++) { v[j] = expf(v[j] - m); sum += v[j]; }
    red[tid] = sum; __syncthreads();
    for (int s = 128; s > 0; s >>= 1) { if (tid < s) red[tid] += red[tid+s]; __syncthreads(); }
    float inv = 1.f / red[0];
#pragma unroll
    for (int j = 0; j < 8; j++) x[tid + j*256] = v[j] * inv;
}

// ---------------- LayerNorm over 1280 ----------------
__global__ __launch_bounds__(256) void layernorm_kernel(const float* __restrict__ x,
    const float* __restrict__ g, const float* __restrict__ b, float* __restrict__ y)
{
    __shared__ float buf[PLMD];
    __shared__ float red[256];
    long row = blockIdx.x;
    const float* xr = x + row*PLMD;
    int tid = threadIdx.x;
    float s = 0.f;
    for (int i = tid; i < PLMD; i += 256) { float t = xr[i]; buf[i] = t; s += t; }
    red[tid] = s; __syncthreads();
    for (int st = 128; st > 0; st >>= 1) { if (tid < st) red[tid] += red[tid+st]; __syncthreads(); }
    float mu = red[0] * (1.f/PLMD); __syncthreads();
    float vs = 0.f;
    for (int i = tid; i < PLMD; i += 256) { float d = buf[i] - mu; vs += d*d; }
    red[tid] = vs; __syncthreads();
    for (int st = 128; st > 0; st >>= 1) { if (tid < st) red[tid] += red[tid+st]; __syncthreads(); }
    float rstd = rsqrtf(red[0] * (1.f/PLMD) + 1e-5f);
    float* yr = y + row*PLMD;
    for (int i = tid; i < PLMD; i += 256) yr[i] = (buf[i] - mu) * rstd * g[i] + b[i];
}

// ---------------- launch ----------------
extern "C" void kernel_launch(void* const* d_in, const int* in_sizes, int n_in,
                              void* d_out, int out_size)
{
    const float* s_repre = (const float*)d_in[0];
    const float* plm     = (const float*)d_in[1];
    const float* Wq = (const float*)d_in[2];  const float* bq = (const float*)d_in[3];
    const float* Wk = (const float*)d_in[4];  const float* bk = (const float*)d_in[5];
    const float* Wv = (const float*)d_in[6];  const float* bv = (const float*)d_in[7];
    const float* Wo = (const float*)d_in[8];  const float* bo = (const float*)d_in[9];
    const float* lng = (const float*)d_in[10]; const float* lnb = (const float*)d_in[11];
    const float* Wd = (const float*)d_in[12]; const float* bd = (const float*)d_in[13];
    const float* Wu = (const float*)d_in[14]; const float* bu = (const float*)d_in[15];

    float* out  = (float*)d_out;
    float* attn = out + OUT_ELEMS;   // tuple order: (out, attention)

    float *qp,*kp,*vp,*qh,*kh,*vt,*av,*vals,*x,*ln,*ff;
    cudaGetSymbolAddress((void**)&qp, g_qp);
    cudaGetSymbolAddress((void**)&kp, g_kp);
    cudaGetSymbolAddress((void**)&vp, g_vp);
    cudaGetSymbolAddress((void**)&qh, g_qh);
    cudaGetSymbolAddress((void**)&kh, g_kh);
    cudaGetSymbolAddress((void**)&vt, g_vt);
    cudaGetSymbolAddress((void**)&av, g_av);
    cudaGetSymbolAddress((void**)&vals, g_vals);
    cudaGetSymbolAddress((void**)&x, g_x);
    cudaGetSymbolAddress((void**)&ln, g_ln);
    cudaGetSymbolAddress((void**)&ff, g_ff);

    const int tot = ROWS*EMB;

    // QKV projections:  q = plm @ Wq^T + bq ; k,v from s_repre
    gemm_kernel<0,128,128,8,8><<<dim3(EMB/128, ROWS/128, 1), 256>>>(
        plm, Wq, bq, nullptr, qp, ROWS, EMB, PLMD, PLMD,1, PLMD,1, EMB, 0,0,0, 1.f);
    gemm_kernel<0,128,128,8,8><<<dim3(EMB/128, ROWS/128, 1), 256>>>(
        s_repre, Wk, bk, nullptr, kp, ROWS, EMB, SD, SD,1, SD,1, EMB, 0,0,0, 1.f);
    gemm_kernel<0,128,128,8,8><<<dim3(EMB/128, ROWS/128, 1), 256>>>(
        s_repre, Wv, bv, nullptr, vp, ROWS, EMB, SD, SD,1, SD,1, EMB, 0,0,0, 1.f);

    // head split + RoPE (q,k) ; V transposed to [B,H,D,S]
    head_split_kernel<1><<<(tot+255)/256, 256>>>(qp, qh);
    head_split_kernel<1><<<(tot+255)/256, 256>>>(kp, kh);
    head_split_kernel<2><<<(tot+255)/256, 256>>>(vp, vt);

    // logits = Q @ K^T / 8  -> written straight into d_out attention region
    gemm_kernel<0,128,128,8,8><<<dim3(SEQ/128, SEQ/128, BATCH*NH), 256>>>(
        qh, kh, nullptr, nullptr, attn, SEQ, SEQ, HD,
        HD,1, HD,1, SEQ, (long)SEQ*HD, (long)SEQ*HD, (long)SEQ*SEQ, 0.125f);

    // softmax in place (these ARE the attention outputs)
    softmax_kernel<<<BATCH*NH*SEQ, 256>>>(attn);

    // AV = P @ V  (B = V^T stored [B,H,D,S] -> coalesced)
    gemm_kernel<0,64,64,4,4><<<dim3(HD/64, SEQ/64, BATCH*NH), 256>>>(
        attn, vt, nullptr, nullptr, av, SEQ, HD, SEQ,
        SEQ,1, SEQ,1, HD, (long)SEQ*SEQ, (long)HD*SEQ, (long)SEQ*HD, 1.f);

    // merge heads [B,H,S,D] -> [B,S,E]
    merge_heads_kernel<<<(tot+255)/256, 256>>>(av, vals);

    // o = vals @ Wo^T + bo + plm  (residual fused)
    gemm_kernel<1,128,128,8,8><<<dim3(PLMD/128, ROWS/128, 1), 256>>>(
        vals, Wo, bo, plm, x, ROWS, PLMD, EMB, EMB,1, EMB,1, PLMD, 0,0,0, 1.f);

    // LayerNorm
    layernorm_kernel<<<ROWS, 256>>>(x, lng, lnb, ln);

    // FFN: gelu(ln @ Wd^T + bd)
    gemm_kernel<2,128,128,8,8><<<dim3(FFD/128, ROWS/128, 1), 256>>>(
        ln, Wd, bd, nullptr, ff, ROWS, FFD, PLMD, PLMD,1, PLMD,1, FFD, 0,0,0, 1.f);

    // out = ff @ Wu^T + bu + ln  (residual fused), written to d_out
    gemm_kernel<1,128,128,8,8><<<dim3(PLMD/128, ROWS/128, 1), 256>>>(
        ff, Wu, bu, ln, out, ROWS, PLMD, FFD, FFD,1, FFD,1, PLMD, 0,0,0, 1.f);
}

// round 2
// speedup vs baseline: 2.6734x; 2.6734x over previous
#include <cuda_runtime.h>
#include <math.h>
#include <stdint.h>

#define BATCH 2
#define SEQ   2048
#define NH    12
#define HD    64
#define EMB   768     // NH*HD
#define PLMD  1280
#define SD    128
#define FFD   640
#define ROWS  (BATCH*SEQ)                 // 4096
#define OUT_ELEMS ((long)ROWS*PLMD)       // 5,242,880
#define LOG2_10000 13.287712379549449f

// ---------------- scratch (static __device__, no allocation) ----------------
__device__ __align__(16) float g_qp[ROWS*EMB];
__device__ __align__(16) float g_kp[ROWS*EMB];
__device__ __align__(16) float g_vp[ROWS*EMB];
__device__ __align__(16) float g_qh[ROWS*EMB];   // [B,H,S,D] roped
__device__ __align__(16) float g_kh[ROWS*EMB];   // [B,H,S,D] roped
__device__ __align__(16) float g_vt[ROWS*EMB];   // [B,H,D,S]
__device__ __align__(16) float g_av[ROWS*EMB];   // [B,H,S,D]
__device__ __align__(16) float g_vals[ROWS*EMB]; // [B,S,E]
__device__ __align__(16) float g_x[ROWS*PLMD];
__device__ __align__(16) float g_ln[ROWS*PLMD];
__device__ __align__(16) float g_ff[ROWS*FFD];

// ---------------- TF32 helpers ----------------
__device__ __forceinline__ uint32_t f2tf32(float x) {
    uint32_t u;
    asm("cvt.rna.tf32.f32 %0, %1;" : "=r"(u) : "f"(x));
    return u;
}

__device__ __forceinline__ void mma_tf32(float* c, const uint32_t* a, const uint32_t* b) {
    asm volatile("mma.sync.aligned.m16n8k8.row.col.f32.tf32.tf32.f32 "
        "{%0,%1,%2,%3}, {%4,%5,%6,%7}, {%8,%9}, {%0,%1,%2,%3};"
        : "+f"(c[0]), "+f"(c[1]), "+f"(c[2]), "+f"(c[3])
        : "r"(a[0]), "r"(a[1]), "r"(a[2]), "r"(a[3]), "r"(b[0]), "r"(b[1]));
}

// ---------------- TF32 tensor-core GEMM: C = alpha*A@B^T (+bias)(+extra)(gelu) ----
// A element (m,k) at A[m*sAm + k]  (k-contiguous!), B element (n,k) at B[n*sBn + k].
// EPI: 0 = (+bias), 1 = +bias+extra, 2 = gelu(+bias)
// 256 threads = 8 warps. WARPS_M*WARPS_N must be 8.
template<int EPI, int BM, int BN, int WARPS_M, int WARPS_N>
__global__ __launch_bounds__(256)
void gemm_tf32(const float* __restrict__ A, const float* __restrict__ B,
               const float* __restrict__ bias, const float* __restrict__ extra,
               float* __restrict__ C,
               int K, int sAm, int sBn, int ldc,
               long zA, long zB, long zC, float alpha)
{
    constexpr int BK  = 16;
    constexpr int LDSW = 20;                 // padded smem row stride (words)
    constexpr int WM = BM / WARPS_M, WN = BN / WARPS_N;
    constexpr int MF = WM / 16, NF = WN / 8; // m16n8k8 fragments per warp
    __shared__ uint32_t As[BM * LDSW];
    __shared__ uint32_t Bs[BN * LDSW];

    const int tid  = threadIdx.x;
    const int lane = tid & 31;
    const int warp = tid >> 5;
    const int wm = warp % WARPS_M, wn = warp / WARPS_M;
    const int row0 = blockIdx.y * BM, col0 = blockIdx.x * BN;
    A += (long)blockIdx.z * zA + (long)row0 * sAm;
    B += (long)blockIdx.z * zB + (long)col0 * sBn;
    C += (long)blockIdx.z * zC;

    const int r  = lane >> 2;   // 0..7
    const int cq = lane & 3;    // 0..3

    float acc[MF][NF][4];
#pragma unroll
    for (int m = 0; m < MF; m++)
#pragma unroll
        for (int n = 0; n < NF; n++)
#pragma unroll
            for (int j = 0; j < 4; j++) acc[m][n][j] = 0.f;

    for (int k0 = 0; k0 < K; k0 += BK) {
        // stage A tile (BM x 16) as tf32
#pragma unroll
        for (int i = 0; i < BM/64; i++) {
            int idx = tid + i*256;
            int row = idx >> 2, f = idx & 3;
            float4 v = *reinterpret_cast<const float4*>(A + (long)row*sAm + k0 + f*4);
            uint4 u;
            u.x = f2tf32(v.x); u.y = f2tf32(v.y); u.z = f2tf32(v.z); u.w = f2tf32(v.w);
            *reinterpret_cast<uint4*>(&As[row*LDSW + f*4]) = u;
        }
        // stage B tile (BN x 16) as tf32
#pragma unroll
        for (int i = 0; i < BN/64; i++) {
            int idx = tid + i*256;
            int row = idx >> 2, f = idx & 3;
            float4 v = *reinterpret_cast<const float4*>(B + (long)row*sBn + k0 + f*4);
            uint4 u;
            u.x = f2tf32(v.x); u.y = f2tf32(v.y); u.z = f2tf32(v.z); u.w = f2tf32(v.w);
            *reinterpret_cast<uint4*>(&Bs[row*LDSW + f*4]) = u;
        }
        __syncthreads();

#pragma unroll
        for (int ks = 0; ks < 2; ks++) {
            const int kk = ks * 8;
            uint32_t af[MF][4], bf[NF][2];
#pragma unroll
            for (int m = 0; m < MF; m++) {
                int base = (wm*WM + m*16 + r)*LDSW + kk + cq;
                af[m][0] = As[base];
                af[m][1] = As[base + 8*LDSW];
                af[m][2] = As[base + 4];
                af[m][3] = As[base + 8*LDSW + 4];
            }
#pragma unroll
            for (int n = 0; n < NF; n++) {
                int base = (wn*WN + n*8 + r)*LDSW + kk + cq;
                bf[n][0] = Bs[base];
                bf[n][1] = Bs[base + 4];
            }
#pragma unroll
            for (int m = 0; m < MF; m++)
#pragma unroll
                for (int n = 0; n < NF; n++)
                    mma_tf32(acc[m][n], af[m], bf[n]);
        }
        __syncthreads();
    }

    // epilogue
#pragma unroll
    for (int m = 0; m < MF; m++) {
#pragma unroll
        for (int n = 0; n < NF; n++) {
            int row = row0 + wm*WM + m*16 + r;
            int col = col0 + wn*WN + n*8 + 2*cq;
            float v0 = alpha * acc[m][n][0];
            float v1 = alpha * acc[m][n][1];
            float v2 = alpha * acc[m][n][2];
            float v3 = alpha * acc[m][n][3];
            if (bias) { v0 += bias[col]; v1 += bias[col+1]; v2 += bias[col]; v3 += bias[col+1]; }
            if (EPI == 1) {
                v0 += extra[(long)row*ldc + col];
                v1 += extra[(long)row*ldc + col + 1];
                v2 += extra[(long)(row+8)*ldc + col];
                v3 += extra[(long)(row+8)*ldc + col + 1];
            }
            if (EPI == 2) {
                v0 = 0.5f * v0 * (1.f + erff(v0 * 0.70710678118654752f));
                v1 = 0.5f * v1 * (1.f + erff(v1 * 0.70710678118654752f));
                v2 = 0.5f * v2 * (1.f + erff(v2 * 0.70710678118654752f));
                v3 = 0.5f * v3 * (1.f + erff(v3 * 0.70710678118654752f));
            }
            *reinterpret_cast<float2*>(&C[(long)row*ldc + col])     = make_float2(v0, v1);
            *reinterpret_cast<float2*>(&C[(long)(row+8)*ldc + col]) = make_float2(v2, v3);
        }
    }
}

// ---------------- head split (+ optional RoPE / V transpose) ----------------
// MODE 1: [B,S,H*D] -> [B,H,S,D] with RoPE
// MODE 2: [B,S,H*D] -> [B,H,D,S]   (for V, so AV B-loads coalesce)
template<int MODE>
__global__ void head_split_kernel(const float* __restrict__ src, float* __restrict__ dst)
{
    int idx = blockIdx.x * blockDim.x + threadIdx.x;
    if (idx >= ROWS*EMB) return;
    int d = idx & 63;
    int s = (idx >> 6) & (SEQ-1);
    int t = idx >> 17;           // 6+11 bits
    int h = t % NH;
    int b = t / NH;
    long srcoff = (long)(b*SEQ + s)*EMB + h*HD + d;
    float val;
    if (MODE == 1) {
        int j = d & 31;
        float inv = exp2f(-(float)j * (LOG2_10000 / 32.0f));  // 10000^{-2j/64}
        float freq = (float)s * inv;
        float sn, c;
        sincosf(freq, &sn, &c);
        float x = src[srcoff];
        float pr = (d < 32) ? -src[srcoff + 32] : src[srcoff - 32];
        val = x*c + pr*sn;
    } else {
        val = src[srcoff];
    }
    if (MODE == 2)
        dst[((long)(b*NH + h)*HD + d)*SEQ + s] = val;
    else
        dst[idx] = val;
}

// ---------------- merge heads: [B,H,S,D] -> [B,S,H*D] ----------------
__global__ void merge_heads_kernel(const float* __restrict__ src, float* __restrict__ dst)
{
    int idx = blockIdx.x * blockDim.x + threadIdx.x;
    if (idx >= ROWS*EMB) return;
    int d = idx & 63;
    int s = (idx >> 6) & (SEQ-1);
    int t = idx >> 17;
    int h = t % NH;
    int b = t / NH;
    dst[(long)(b*SEQ + s)*EMB + h*HD + d] = src[idx];
}

// ---------------- row softmax over 2048 cols, in place ----------------
__global__ __launch_bounds__(256) void softmax_kernel(float* __restrict__ att)
{
    __shared__ float red[256];
    long row = blockIdx.x;
    float* x = att + row * SEQ;
    int tid = threadIdx.x;
    float v[8];
    float m = -1e30f;
#pragma unroll
    for (int j = 0; j < 8; j++) { v[j] = x[tid + j*256]; m = fmaxf(m, v[j]); }
    red[tid] = m; __syncthreads();
    for (int s = 128; s > 0; s >>= 1) { if (tid < s) red[tid] = fmaxf(red[tid], red[tid+s]); __syncthreads(); }
    m = red[0]; __syncthreads();
    float sum = 0.f;
#pragma unroll
    for (int j = 0; j < 8; j++) { v[j] = expf(v[j] - m); sum += v[j]; }
    red[tid] = sum; __syncthreads();
    for (int s = 128; s > 0; s >>= 1) { if (tid < s) red[tid] += red[tid+s]; __syncthreads(); }
    float inv = 1.f / red[0];
#pragma unroll
    for (int j = 0; j < 8; j++) x[tid + j*256] = v[j] * inv;
}

// ---------------- LayerNorm over 1280 ----------------
__global__ __launch_bounds__(256) void layernorm_kernel(const float* __restrict__ x,
    const float* __restrict__ g, const float* __restrict__ b, float* __restrict__ y)
{
    __shared__ float buf[PLMD];
    __shared__ float red[256];
    long row = blockIdx.x;
    const float* xr = x + row*PLMD;
    int tid = threadIdx.x;
    float s = 0.f;
    for (int i = tid; i < PLMD; i += 256) { float t = xr[i]; buf[i] = t; s += t; }
    red[tid] = s; __syncthreads();
    for (int st = 128; st > 0; st >>= 1) { if (tid < st) red[tid] += red[tid+st]; __syncthreads(); }
    float mu = red[0] * (1.f/PLMD); __syncthreads();
    float vs = 0.f;
    for (int i = tid; i < PLMD; i += 256) { float d = buf[i] - mu; vs += d*d; }
    red[tid] = vs; __syncthreads();
    for (int st = 128; st > 0; st >>= 1) { if (tid < st) red[tid] += red[tid+st]; __syncthreads(); }
    float rstd = rsqrtf(red[0] * (1.f/PLMD) + 1e-5f);
    float* yr = y + row*PLMD;
    for (int i = tid; i < PLMD; i += 256) yr[i] = (buf[i] - mu) * rstd * g[i] + b[i];
}

// ---------------- launch ----------------
extern "C" void kernel_launch(void* const* d_in, const int* in_sizes, int n_in,
                              void* d_out, int out_size)
{
    const float* s_repre = (const float*)d_in[0];
    const float* plm     = (const float*)d_in[1];
    const float* Wq = (const float*)d_in[2];  const float* bq = (const float*)d_in[3];
    const float* Wk = (const float*)d_in[4];  const float* bk = (const float*)d_in[5];
    const float* Wv = (const float*)d_in[6];  const float* bv = (const float*)d_in[7];
    const float* Wo = (const float*)d_in[8];  const float* bo = (const float*)d_in[9];
    const float* lng = (const float*)d_in[10]; const float* lnb = (const float*)d_in[11];
    const float* Wd = (const float*)d_in[12]; const float* bd = (const float*)d_in[13];
    const float* Wu = (const float*)d_in[14]; const float* bu = (const float*)d_in[15];

    float* out  = (float*)d_out;
    float* attn = out + OUT_ELEMS;   // tuple order: (out, attention)

    float *qp,*kp,*vp,*qh,*kh,*vt,*av,*vals,*x,*ln,*ff;
    cudaGetSymbolAddress((void**)&qp, g_qp);
    cudaGetSymbolAddress((void**)&kp, g_kp);
    cudaGetSymbolAddress((void**)&vp, g_vp);
    cudaGetSymbolAddress((void**)&qh, g_qh);
    cudaGetSymbolAddress((void**)&kh, g_kh);
    cudaGetSymbolAddress((void**)&vt, g_vt);
    cudaGetSymbolAddress((void**)&av, g_av);
    cudaGetSymbolAddress((void**)&vals, g_vals);
    cudaGetSymbolAddress((void**)&x, g_x);
    cudaGetSymbolAddress((void**)&ln, g_ln);
    cudaGetSymbolAddress((void**)&ff, g_ff);

    const int tot = ROWS*EMB;

    // QKV projections:  q = plm @ Wq^T + bq ; k,v from s_repre
    gemm_tf32<0,128,128,2,4><<<dim3(EMB/128, ROWS/128, 1), 256>>>(
        plm, Wq, bq, nullptr, qp, PLMD, PLMD, PLMD, EMB, 0,0,0, 1.f);
    gemm_tf32<0,128,128,2,4><<<dim3(EMB/128, ROWS/128, 1), 256>>>(
        s_repre, Wk, bk, nullptr, kp, SD, SD, SD, EMB, 0,0,0, 1.f);
    gemm_tf32<0,128,128,2,4><<<dim3(EMB/128, ROWS/128, 1), 256>>>(
        s_repre, Wv, bv, nullptr, vp, SD, SD, SD, EMB, 0,0,0, 1.f);

    // head split + RoPE (q,k) ; V transposed to [B,H,D,S]
    head_split_kernel<1><<<(tot+255)/256, 256>>>(qp, qh);
    head_split_kernel<1><<<(tot+255)/256, 256>>>(kp, kh);
    head_split_kernel<2><<<(tot+255)/256, 256>>>(vp, vt);

    // logits = Q @ K^T / 8  -> written straight into d_out attention region
    gemm_tf32<0,128,128,2,4><<<dim3(SEQ/128, SEQ/128, BATCH*NH), 256>>>(
        qh, kh, nullptr, nullptr, attn, HD, HD, HD, SEQ,
        (long)SEQ*HD, (long)SEQ*HD, (long)SEQ*SEQ, 0.125f);

    // softmax in place (these ARE the attention outputs)
    softmax_kernel<<<BATCH*NH*SEQ, 256>>>(attn);

    // AV = P @ V  (B = V^T stored [B,H,D,S] -> k-contiguous)
    gemm_tf32<0,128,64,4,2><<<dim3(1, SEQ/128, BATCH*NH), 256>>>(
        attn, vt, nullptr, nullptr, av, SEQ, SEQ, SEQ, HD,
        (long)SEQ*SEQ, (long)HD*SEQ, (long)SEQ*HD, 1.f);

    // merge heads [B,H,S,D] -> [B,S,E]
    merge_heads_kernel<<<(tot+255)/256, 256>>>(av, vals);

    // o = vals @ Wo^T + bo + plm  (residual fused)
    gemm_tf32<1,128,128,2,4><<<dim3(PLMD/128, ROWS/128, 1), 256>>>(
        vals, Wo, bo, plm, x, EMB, EMB, EMB, PLMD, 0,0,0, 1.f);

    // LayerNorm
    layernorm_kernel<<<ROWS, 256>>>(x, lng, lnb, ln);

    // FFN: gelu(ln @ Wd^T + bd)
    gemm_tf32<2,128,128,2,4><<<dim3(FFD/128, ROWS/128, 1), 256>>>(
        ln, Wd, bd, nullptr, ff, PLMD, PLMD, PLMD, FFD, 0,0,0, 1.f);

    // out = ff @ Wu^T + bu + ln  (residual fused), written to d_out
    gemm_tf32<1,128,128,2,4><<<dim3(PLMD/128, ROWS/128, 1), 256>>>(
        ff, Wu, bu, ln, out, FFD, FFD, FFD, PLMD, 0,0,0, 1.f);
}

// round 3
// speedup vs baseline: 3.2804x; 1.2271x over previous
#include <cuda_runtime.h>
#include <math.h>
#include <stdint.h>

#define BATCH 2
#define SEQ   2048
#define NH    12
#define HD    64
#define EMB   768     // NH*HD
#define PLMD  1280
#define SD    128
#define FFD   640
#define ROWS  (BATCH*SEQ)                 // 4096
#define OUT_ELEMS ((long)ROWS*PLMD)       // 5,242,880
#define LOG2_10000 13.287712379549449f

// ---------------- scratch (static __device__, no allocation) ----------------
__device__ __align__(16) float g_qp[ROWS*EMB];
__device__ __align__(16) float g_kp[ROWS*EMB];
__device__ __align__(16) float g_vp[ROWS*EMB];
__device__ __align__(16) float g_qh[ROWS*EMB];   // [B,H,S,D] roped
__device__ __align__(16) float g_kh[ROWS*EMB];   // [B,H,S,D] roped
__device__ __align__(16) float g_vt[ROWS*EMB];   // [B,H,D,S]
__device__ __align__(16) float g_av[ROWS*EMB];   // [B,H,S,D]
__device__ __align__(16) float g_vals[ROWS*EMB]; // [B,S,E]
__device__ __align__(16) float g_x[ROWS*PLMD];
__device__ __align__(16) float g_ln[ROWS*PLMD];
__device__ __align__(16) float g_ff[ROWS*FFD];

// ---------------- helpers ----------------
__device__ __forceinline__ uint32_t f2tf32(uint32_t xbits) {
    uint32_t u;
    float f = __uint_as_float(xbits);
    asm("cvt.rna.tf32.f32 %0, %1;" : "=r"(u) : "f"(f));
    return u;
}

__device__ __forceinline__ void mma_tf32(float* c, const uint32_t* a, const uint32_t* b) {
    asm volatile("mma.sync.aligned.m16n8k8.row.col.f32.tf32.tf32.f32 "
        "{%0,%1,%2,%3}, {%4,%5,%6,%7}, {%8,%9}, {%0,%1,%2,%3};"
        : "+f"(c[0]), "+f"(c[1]), "+f"(c[2]), "+f"(c[3])
        : "r"(a[0]), "r"(a[1]), "r"(a[2]), "r"(a[3]), "r"(b[0]), "r"(b[1]));
}

__device__ __forceinline__ void cp_async16(uint32_t smem_dst, const void* gsrc) {
    asm volatile("cp.async.cg.shared.global [%0], [%1], 16;" :: "r"(smem_dst), "l"(gsrc));
}
__device__ __forceinline__ void cp_commit() { asm volatile("cp.async.commit_group;"); }
__device__ __forceinline__ void cp_wait1()  { asm volatile("cp.async.wait_group 1;"); }

// ---------------- TF32 pipelined GEMM: C = alpha*A@B^T (+bias)(+extra)(gelu) ----
// A element (m,k) at A[m*sAm + k]  (k-contiguous), B element (n,k) at B[n*sBn + k].
// EPI: 0 = (+bias), 1 = +bias+extra, 2 = gelu(+bias)
// 256 threads = 8 warps, double-buffered cp.async, BK=32.
template<int EPI, int BM, int BN, int WARPS_M, int WARPS_N>
__global__ __launch_bounds__(256)
void gemm_tf32(const float* __restrict__ A, const float* __restrict__ B,
               const float* __restrict__ bias, const float* __restrict__ extra,
               float* __restrict__ C,
               int K, int sAm, int sBn, int ldc,
               long zA, long zB, long zC, float alpha)
{
    constexpr int BK   = 32;
    constexpr int LDSW = 36;                 // padded smem row stride (words)
    constexpr int WM = BM / WARPS_M, WN = BN / WARPS_N;
    constexpr int MF = WM / 16, NF = WN / 8; // m16n8k8 fragments per warp
    constexpr int ASTG = BM * LDSW;
    constexpr int BSTG = BN * LDSW;

    extern __shared__ uint32_t smem[];
    uint32_t* As = smem;                    // [2][BM*LDSW]
    uint32_t* Bs = smem + 2 * ASTG;         // [2][BN*LDSW]

    const int tid  = threadIdx.x;
    const int lane = tid & 31;
    const int warp = tid >> 5;
    const int wm = warp % WARPS_M, wn = warp / WARPS_M;
    const int row0 = blockIdx.y * BM, col0 = blockIdx.x * BN;
    A += (long)blockIdx.z * zA + (long)row0 * sAm;
    B += (long)blockIdx.z * zB + (long)col0 * sBn;
    C += (long)blockIdx.z * zC;

    const uint32_t smem_base = (uint32_t)__cvta_generic_to_shared(smem);

    const int r  = lane >> 2;   // 0..7
    const int cq = lane & 3;    // 0..3

    float acc[MF][NF][4];
#pragma unroll
    for (int m = 0; m < MF; m++)
#pragma unroll
        for (int n = 0; n < NF; n++)
#pragma unroll
            for (int j = 0; j < 4; j++) acc[m][n][j] = 0.f;

    // per-thread load coordinates: BK=32 floats/row = 8 float4; 256 threads
    const int lrow = tid >> 3;       // 0..31
    const int lf   = (tid & 7) * 4;  // word offset within row (0,4,..,28)

    auto prefetch = [&](int stage, int k0) {
#pragma unroll
        for (int i = 0; i < BM/32; i++) {
            int row = lrow + i*32;
            cp_async16(smem_base + (stage*ASTG + row*LDSW + lf)*4,
                       A + (long)row*sAm + k0 + lf);
        }
#pragma unroll
        for (int i = 0; i < BN/32; i++) {
            int row = lrow + i*32;
            cp_async16(smem_base + ((2*ASTG) + stage*BSTG + row*LDSW + lf)*4,
                       B + (long)row*sBn + k0 + lf);
        }
    };

    const int nk = K / BK;
    prefetch(0, 0);
    cp_commit();

    for (int kt = 0; kt < nk; kt++) {
        const int stage = kt & 1;
        if (kt + 1 < nk) prefetch(stage ^ 1, (kt+1) * BK);
        cp_commit();
        cp_wait1();
        __syncthreads();

        const uint32_t* Ast = As + stage * ASTG;
        const uint32_t* Bst = Bs + stage * BSTG;
#pragma unroll
        for (int ks = 0; ks < BK/8; ks++) {
            const int kk = ks * 8;
            uint32_t af[MF][4], bf[NF][2];
#pragma unroll
            for (int m = 0; m < MF; m++) {
                int base = (wm*WM + m*16 + r)*LDSW + kk + cq;
                af[m][0] = f2tf32(Ast[base]);
                af[m][1] = f2tf32(Ast[base + 8*LDSW]);
                af[m][2] = f2tf32(Ast[base + 4]);
                af[m][3] = f2tf32(Ast[base + 8*LDSW + 4]);
            }
#pragma unroll
            for (int n = 0; n < NF; n++) {
                int base = (wn*WN + n*8 + r)*LDSW + kk + cq;
                bf[n][0] = f2tf32(Bst[base]);
                bf[n][1] = f2tf32(Bst[base + 4]);
            }
#pragma unroll
            for (int m = 0; m < MF; m++)
#pragma unroll
                for (int n = 0; n < NF; n++)
                    mma_tf32(acc[m][n], af[m], bf[n]);
        }
        __syncthreads();
    }

    // epilogue
#pragma unroll
    for (int m = 0; m < MF; m++) {
#pragma unroll
        for (int n = 0; n < NF; n++) {
            int row = row0 + wm*WM + m*16 + r;
            int col = col0 + wn*WN + n*8 + 2*cq;
            float v0 = alpha * acc[m][n][0];
            float v1 = alpha * acc[m][n][1];
            float v2 = alpha * acc[m][n][2];
            float v3 = alpha * acc[m][n][3];
            if (bias) { v0 += bias[col]; v1 += bias[col+1]; v2 += bias[col]; v3 += bias[col+1]; }
            if (EPI == 1) {
                v0 += extra[(long)row*ldc + col];
                v1 += extra[(long)row*ldc + col + 1];
                v2 += extra[(long)(row+8)*ldc + col];
                v3 += extra[(long)(row+8)*ldc + col + 1];
            }
            if (EPI == 2) {
                v0 = 0.5f * v0 * (1.f + erff(v0 * 0.70710678118654752f));
                v1 = 0.5f * v1 * (1.f + erff(v1 * 0.70710678118654752f));
                v2 = 0.5f * v2 * (1.f + erff(v2 * 0.70710678118654752f));
                v3 = 0.5f * v3 * (1.f + erff(v3 * 0.70710678118654752f));
            }
            *reinterpret_cast<float2*>(&C[(long)row*ldc + col])     = make_float2(v0, v1);
            *reinterpret_cast<float2*>(&C[(long)(row+8)*ldc + col]) = make_float2(v2, v3);
        }
    }
}

// ---------------- head split (+ optional RoPE / V transpose) ----------------
template<int MODE>
__global__ void head_split_kernel(const float* __restrict__ src, float* __restrict__ dst)
{
    int idx = blockIdx.x * blockDim.x + threadIdx.x;
    if (idx >= ROWS*EMB) return;
    int d = idx & 63;
    int s = (idx >> 6) & (SEQ-1);
    int t = idx >> 17;           // 6+11 bits
    int h = t % NH;
    int b = t / NH;
    long srcoff = (long)(b*SEQ + s)*EMB + h*HD + d;
    float val;
    if (MODE == 1) {
        int j = d & 31;
        float inv = exp2f(-(float)j * (LOG2_10000 / 32.0f));  // 10000^{-2j/64}
        float freq = (float)s * inv;
        float sn, c;
        sincosf(freq, &sn, &c);
        float x = src[srcoff];
        float pr = (d < 32) ? -src[srcoff + 32] : src[srcoff - 32];
        val = x*c + pr*sn;
    } else {
        val = src[srcoff];
    }
    if (MODE == 2)
        dst[((long)(b*NH + h)*HD + d)*SEQ + s] = val;
    else
        dst[idx] = val;
}

// ---------------- merge heads: [B,H,S,D] -> [B,S,H*D] ----------------
__global__ void merge_heads_kernel(const float* __restrict__ src, float* __restrict__ dst)
{
    int idx = blockIdx.x * blockDim.x + threadIdx.x;
    if (idx >= ROWS*EMB) return;
    int d = idx & 63;
    int s = (idx >> 6) & (SEQ-1);
    int t = idx >> 17;
    int h = t % NH;
    int b = t / NH;
    dst[(long)(b*SEQ + s)*EMB + h*HD + d] = src[idx];
}

// ---------------- row softmax over 2048 cols, in place ----------------
__global__ __launch_bounds__(256) void softmax_kernel(float* __restrict__ att)
{
    __shared__ float red[256];
    long row = blockIdx.x;
    float* x = att + row * SEQ;
    int tid = threadIdx.x;
    float v[8];
    float m = -1e30f;
#pragma unroll
    for (int j = 0; j < 8; j++) { v[j] = x[tid + j*256]; m = fmaxf(m, v[j]); }
    red[tid] = m; __syncthreads();
    for (int s = 128; s > 0; s >>= 1) { if (tid < s) red[tid] = fmaxf(red[tid], red[tid+s]); __syncthreads(); }
    m = red[0]; __syncthreads();
    float sum = 0.f;
#pragma unroll
    for (int j = 0; j < 8; j++) { v[j] = expf(v[j] - m); sum += v[j]; }
    red[tid] = sum; __syncthreads();
    for (int s = 128; s > 0; s >>= 1) { if (tid < s) red[tid] += red[tid+s]; __syncthreads(); }
    float inv = 1.f / red[0];
#pragma unroll
    for (int j = 0; j < 8; j++) x[tid + j*256] = v[j] * inv;
}

// ---------------- LayerNorm over 1280 ----------------
__global__ __launch_bounds__(256) void layernorm_kernel(const float* __restrict__ x,
    const float* __restrict__ g, const float* __restrict__ b, float* __restrict__ y)
{
    __shared__ float buf[PLMD];
    __shared__ float red[256];
    long row = blockIdx.x;
    const float* xr = x + row*PLMD;
    int tid = threadIdx.x;
    float s = 0.f;
    for (int i = tid; i < PLMD; i += 256) { float t = xr[i]; buf[i] = t; s += t; }
    red[tid] = s; __syncthreads();
    for (int st = 128; st > 0; st >>= 1) { if (tid < st) red[tid] += red[tid+st]; __syncthreads(); }
    float mu = red[0] * (1.f/PLMD); __syncthreads();
    float vs = 0.f;
    for (int i = tid; i < PLMD; i += 256) { float d = buf[i] - mu; vs += d*d; }
    red[tid] = vs; __syncthreads();
    for (int st = 128; st > 0; st >>= 1) { if (tid < st) red[tid] += red[tid+st]; __syncthreads(); }
    float rstd = rsqrtf(red[0] * (1.f/PLMD) + 1e-5f);
    float* yr = y + row*PLMD;
    for (int i = tid; i < PLMD; i += 256) yr[i] = (buf[i] - mu) * rstd * g[i] + b[i];
}

// ---------------- launch ----------------
extern "C" void kernel_launch(void* const* d_in, const int* in_sizes, int n_in,
                              void* d_out, int out_size)
{
    const float* s_repre = (const float*)d_in[0];
    const float* plm     = (const float*)d_in[1];
    const float* Wq = (const float*)d_in[2];  const float* bq = (const float*)d_in[3];
    const float* Wk = (const float*)d_in[4];  const float* bk = (const float*)d_in[5];
    const float* Wv = (const float*)d_in[6];  const float* bv = (const float*)d_in[7];
    const float* Wo = (const float*)d_in[8];  const float* bo = (const float*)d_in[9];
    const float* lng = (const float*)d_in[10]; const float* lnb = (const float*)d_in[11];
    const float* Wd = (const float*)d_in[12]; const float* bd = (const float*)d_in[13];
    const float* Wu = (const float*)d_in[14]; const float* bu = (const float*)d_in[15];

    float* out  = (float*)d_out;
    float* attn = out + OUT_ELEMS;   // tuple order: (out, attention)

    float *qp,*kp,*vp,*qh,*kh,*vt,*av,*vals,*x,*ln,*ff;
    cudaGetSymbolAddress((void**)&qp, g_qp);
    cudaGetSymbolAddress((void**)&kp, g_kp);
    cudaGetSymbolAddress((void**)&vp, g_vp);
    cudaGetSymbolAddress((void**)&qh, g_qh);
    cudaGetSymbolAddress((void**)&kh, g_kh);
    cudaGetSymbolAddress((void**)&vt, g_vt);
    cudaGetSymbolAddress((void**)&av, g_av);
    cudaGetSymbolAddress((void**)&vals, g_vals);
    cudaGetSymbolAddress((void**)&x, g_x);
    cudaGetSymbolAddress((void**)&ln, g_ln);
    cudaGetSymbolAddress((void**)&ff, g_ff);

    // dynamic smem sizes: 2 stages * (BM+BN) * 36 words * 4B
    const int S_128_128 = 2 * (128 + 128) * 36 * 4;   // 73728
    const int S_128_64  = 2 * (128 + 64)  * 36 * 4;   // 55296
    cudaFuncSetAttribute(gemm_tf32<0,128,128,2,4>, cudaFuncAttributeMaxDynamicSharedMemorySize, S_128_128);
    cudaFuncSetAttribute(gemm_tf32<1,128,128,2,4>, cudaFuncAttributeMaxDynamicSharedMemorySize, S_128_128);
    cudaFuncSetAttribute(gemm_tf32<2,128,128,2,4>, cudaFuncAttributeMaxDynamicSharedMemorySize, S_128_128);
    cudaFuncSetAttribute(gemm_tf32<0,128,64,4,2>,  cudaFuncAttributeMaxDynamicSharedMemorySize, S_128_64);

    const int tot = ROWS*EMB;

    // QKV projections:  q = plm @ Wq^T + bq ; k,v from s_repre
    gemm_tf32<0,128,128,2,4><<<dim3(EMB/128, ROWS/128, 1), 256, S_128_128>>>(
        plm, Wq, bq, nullptr, qp, PLMD, PLMD, PLMD, EMB, 0,0,0, 1.f);
    gemm_tf32<0,128,128,2,4><<<dim3(EMB/128, ROWS/128, 1), 256, S_128_128>>>(
        s_repre, Wk, bk, nullptr, kp, SD, SD, SD, EMB, 0,0,0, 1.f);
    gemm_tf32<0,128,128,2,4><<<dim3(EMB/128, ROWS/128, 1), 256, S_128_128>>>(
        s_repre, Wv, bv, nullptr, vp, SD, SD, SD, EMB, 0,0,0, 1.f);

    // head split + RoPE (q,k) ; V transposed to [B,H,D,S]
    head_split_kernel<1><<<(tot+255)/256, 256>>>(qp, qh);
    head_split_kernel<1><<<(tot+255)/256, 256>>>(kp, kh);
    head_split_kernel<2><<<(tot+255)/256, 256>>>(vp, vt);

    // logits = Q @ K^T / 8  -> written straight into d_out attention region
    gemm_tf32<0,128,128,2,4><<<dim3(SEQ/128, SEQ/128, BATCH*NH), 256, S_128_128>>>(
        qh, kh, nullptr, nullptr, attn, HD, HD, HD, SEQ,
        (long)SEQ*HD, (long)SEQ*HD, (long)SEQ*SEQ, 0.125f);

    // softmax in place (these ARE the attention outputs)
    softmax_kernel<<<BATCH*NH*SEQ, 256>>>(attn);

    // AV = P @ V  (B = V^T stored [B,H,D,S] -> k-contiguous)
    gemm_tf32<0,128,64,4,2><<<dim3(1, SEQ/128, BATCH*NH), 256, S_128_64>>>(
        attn, vt, nullptr, nullptr, av, SEQ, SEQ, SEQ, HD,
        (long)SEQ*SEQ, (long)HD*SEQ, (long)SEQ*HD, 1.f);

    // merge heads [B,H,S,D] -> [B,S,E]
    merge_heads_kernel<<<(tot+255)/256, 256>>>(av, vals);

    // o = vals @ Wo^T + bo + plm  (residual fused)
    gemm_tf32<1,128,128,2,4><<<dim3(PLMD/128, ROWS/128, 1), 256, S_128_128>>>(
        vals, Wo, bo, plm, x, EMB, EMB, EMB, PLMD, 0,0,0, 1.f);

    // LayerNorm
    layernorm_kernel<<<ROWS, 256>>>(x, lng, lnb, ln);

    // FFN: gelu(ln @ Wd^T + bd)
    gemm_tf32<2,128,128,2,4><<<dim3(FFD/128, ROWS/128, 1), 256, S_128_128>>>(
        ln, Wd, bd, nullptr, ff, PLMD, PLMD, PLMD, FFD, 0,0,0, 1.f);

    // out = ff @ Wu^T + bu + ln  (residual fused), written to d_out
    gemm_tf32<1,128,128,2,4><<<dim3(PLMD/128, ROWS/128, 1), 256, S_128_128>>>(
        ff, Wu, bu, ln, out, FFD, FFD, FFD, PLMD, 0,0,0, 1.f);
}